// round 16
// baseline (speedup 1.0000x reference)
#include <cuda_runtime.h>
#include <cuda_fp16.h>
#include <cstdint>

#define NN 100000
#define DD 128
#define NE 1600000
#define BN_EPS 1e-5f
#define SCAN_B 512
#define NBLK1 ((NN + SCAN_B - 1) / SCAN_B)   // 196

// Scratch (device globals; float4/uint2 => alignment for wide ld/st)
__device__ float4 g_h4[(size_t)NN * 32];      // 51.2 MB  (GEMM1 output)
__device__ uint2  g_xh2[(size_t)NN * 32];     // 25.6 MB fp16 mirror of x
__device__ float  g_colsum[DD];
__device__ float  g_colsq[DD];
__device__ float  g_bncoef[2 * DD];
__device__ int    g_is64;
// CSR scratch
__device__ int    g_deg[NN];
__device__ int    g_off[NN];
__device__ int    g_cur[NN];
__device__ int    g_adj[2 * NE];              // 12.8 MB
__device__ int    g_bsum[NBLK1];
__device__ int    g_bpre[NBLK1];

// ---------------------------------------------------------------------------
__global__ void detect_kernel(const long long* __restrict__ ei) {
    long long ok = 1;
    #pragma unroll
    for (int i = 0; i < 16; i++) {
        long long v = ei[i];
        if (v < 0 || v >= NN) ok = 0;
    }
    g_is64 = (int)ok;
}

__device__ __forceinline__ void load_edge(const void* ei_raw, int e, int& s, int& d) {
    if (g_is64) {
        const long long* ei = (const long long*)ei_raw;
        s = (int)ei[e]; d = (int)ei[NE + e];
    } else {
        const int* ei = (const int*)ei_raw;
        s = ei[e]; d = ei[NE + e];
    }
}

// ---------------------------------------------------------------------------
// fused: fp16 mirror of x + zero degrees + zero BN stat accumulators
// ---------------------------------------------------------------------------
__global__ void prep_kernel(const float4* __restrict__ x) {
    int i = blockIdx.x * blockDim.x + threadIdx.x;
    if (i < NN * 32) {
        float4 v = x[i];
        half2 lo = __floats2half2_rn(v.x, v.y);
        half2 hi = __floats2half2_rn(v.z, v.w);
        uint2 u;
        u.x = *reinterpret_cast<unsigned int*>(&lo);
        u.y = *reinterpret_cast<unsigned int*>(&hi);
        g_xh2[i] = u;
    }
    if (i < NN) g_deg[i] = 0;
    if (i < DD) { g_colsum[i] = 0.0f; g_colsq[i] = 0.0f; }
}

// ---------------------------------------------------------------------------
__global__ void hist_kernel(const void* __restrict__ ei_raw) {
    int e = blockIdx.x * blockDim.x + threadIdx.x;
    if (e >= NE) return;
    int s, d; load_edge(ei_raw, e, s, d);
    atomicAdd(&g_deg[d], 1);
    atomicAdd(&g_deg[s], 1);
}

// ---------------------------------------------------------------------------
__global__ void scan_block_kernel() {
    __shared__ int sh[SCAN_B];
    int tid = threadIdx.x;
    int i = blockIdx.x * SCAN_B + tid;
    int v = (i < NN) ? g_deg[i] : 0;
    sh[tid] = v;
    __syncthreads();
    #pragma unroll
    for (int o = 1; o < SCAN_B; o <<= 1) {
        int t = (tid >= o) ? sh[tid - o] : 0;
        __syncthreads();
        sh[tid] += t;
        __syncthreads();
    }
    if (i < NN) g_off[i] = sh[tid] - v;
    if (tid == SCAN_B - 1) g_bsum[blockIdx.x] = sh[tid];
}

__global__ void scan_top_kernel() {
    __shared__ int sh[256];
    int tid = threadIdx.x;
    int v = (tid < NBLK1) ? g_bsum[tid] : 0;
    sh[tid] = v;
    __syncthreads();
    #pragma unroll
    for (int o = 1; o < 256; o <<= 1) {
        int t = (tid >= o) ? sh[tid - o] : 0;
        __syncthreads();
        sh[tid] += t;
        __syncthreads();
    }
    if (tid < NBLK1) g_bpre[tid] = sh[tid] - v;
}

__global__ void scan_add_kernel() {
    int i = blockIdx.x * SCAN_B + threadIdx.x;
    if (i < NN) {
        int o = g_off[i] + g_bpre[blockIdx.x];
        g_off[i] = o;
        g_cur[i] = o;
    }
}

// ---------------------------------------------------------------------------
__global__ void fill_kernel(const void* __restrict__ ei_raw) {
    int e = blockIdx.x * blockDim.x + threadIdx.x;
    if (e >= NE) return;
    int s, d; load_edge(ei_raw, e, s, d);
    int p0 = atomicAdd(&g_cur[d], 1);
    g_adj[p0] = s;
    int p1 = atomicAdd(&g_cur[s], 1);
    g_adj[p1] = d;
}

// ===========================================================================
// FUSED gather + FFMA2 GEMM1:
//   hpre(tile) = (2+eps)*x + neighbor-sum  (gathered straight into smem,
//   transposed; neighbor rows from fp16 mirror = L2-resident, no DRAM
//   round-trip through a hpre buffer)
//   g_h = hpre @ W1^T + b1, plus per-column sum/sumsq for BN.
// 256 threads (8 warps), tile 64 rows x 128 cols. smem ~107 KB => 2 CTAs/SM.
// ===========================================================================
#define ZT_S 66   // Zt row stride (64 rows + 2 pad)

__global__ void __launch_bounds__(256, 2)
fused_gemm1_kernel(const float4* __restrict__ x, const void* __restrict__ eps_p,
                   const float* __restrict__ W, const float* __restrict__ bias,
                   float4* __restrict__ out)
{
    extern __shared__ float sm[];
    float* Zt   = sm;                     // [128][ZT_S] transposed: Zt[k*ZT_S+row]
    float* Ws   = sm + 128 * ZT_S;        // [128][132], Ws[k*132+j] = W[j][k]
    float* rsum = Ws + 128 * 132;         // [8][128]
    float* rsq  = rsum + 8 * 128;         // [8][128]

    const int tid  = threadIdx.x;
    const int lane = tid & 31;
    const int warp = tid >> 5;
    const int row0 = blockIdx.x * 64;
    const float sc = 2.0f + *(const float*)eps_p;

    #pragma unroll 8
    for (int idx = tid; idx < 128 * 128; idx += 256) {
        int j = idx >> 7, k = idx & 127;
        Ws[k * 132 + j] = W[idx];
    }

    // ---- gather phase: warp handles rows row0+warp*8 .. +7; lane owns chunk lane
    #pragma unroll 1
    for (int i = 0; i < 8; i++) {
        int r = warp * 8 + i;
        int row = row0 + r;
        float4 acc = make_float4(0.f, 0.f, 0.f, 0.f);
        if (row < NN) {
            float4 xv = x[(size_t)row * 32 + lane];
            acc = make_float4(xv.x * sc, xv.y * sc, xv.z * sc, xv.w * sc);
            const int* adj = g_adj + g_off[row];
            int deg = g_deg[row];
            int j = 0;
            for (; j + 8 <= deg; j += 8) {
                int n[8];
                #pragma unroll
                for (int q = 0; q < 8; q++) n[q] = adj[j + q];
                uint2 u[8];
                #pragma unroll
                for (int q = 0; q < 8; q++) u[q] = g_xh2[(size_t)n[q] * 32 + lane];
                #pragma unroll
                for (int q = 0; q < 8; q++) {
                    float2 a = __half22float2(*reinterpret_cast<half2*>(&u[q].x));
                    float2 b = __half22float2(*reinterpret_cast<half2*>(&u[q].y));
                    acc.x += a.x; acc.y += a.y; acc.z += b.x; acc.w += b.y;
                }
            }
            for (; j < deg; j++) {
                uint2 u0 = g_xh2[(size_t)adj[j] * 32 + lane];
                float2 a0 = __half22float2(*reinterpret_cast<half2*>(&u0.x));
                float2 b0 = __half22float2(*reinterpret_cast<half2*>(&u0.y));
                acc.x += a0.x; acc.y += a0.y; acc.z += b0.x; acc.w += b0.y;
            }
        }
        int c = lane * 4;
        Zt[(c + 0) * ZT_S + r] = acc.x;
        Zt[(c + 1) * ZT_S + r] = acc.y;
        Zt[(c + 2) * ZT_S + r] = acc.z;
        Zt[(c + 3) * ZT_S + r] = acc.w;
    }
    __syncthreads();

    // ---- FFMA2 mainloop: acc[c*4+p] = packed pair {row 2p, row 2p+1} of col lane*4+c
    unsigned long long acc[16];
    #pragma unroll
    for (int i = 0; i < 16; i++) acc[i] = 0ULL;

    const float* ztbase = Zt + warp * 8;
    #pragma unroll 2
    for (int k = 0; k < 128; k++) {
        unsigned long long zp[4];
        #pragma unroll
        for (int p = 0; p < 4; p++)
            zp[p] = *reinterpret_cast<const unsigned long long*>(&ztbase[k * ZT_S + 2 * p]);
        float4 bv = *reinterpret_cast<const float4*>(&Ws[k * 132 + lane * 4]);
        unsigned long long wp[4];
        asm("mov.b64 %0, {%1,%1};" : "=l"(wp[0]) : "r"(__float_as_uint(bv.x)));
        asm("mov.b64 %0, {%1,%1};" : "=l"(wp[1]) : "r"(__float_as_uint(bv.y)));
        asm("mov.b64 %0, {%1,%1};" : "=l"(wp[2]) : "r"(__float_as_uint(bv.z)));
        asm("mov.b64 %0, {%1,%1};" : "=l"(wp[3]) : "r"(__float_as_uint(bv.w)));
        #pragma unroll
        for (int c = 0; c < 4; c++) {
            #pragma unroll
            for (int p = 0; p < 4; p++) {
                asm("fma.rn.f32x2 %0, %1, %2, %3;"
                    : "=l"(acc[c * 4 + p])
                    : "l"(zp[p]), "l"(wp[c]), "l"(acc[c * 4 + p]));
            }
        }
    }

    float4 bb = *reinterpret_cast<const float4*>(&bias[lane * 4]);

    float4 s  = make_float4(0.f, 0.f, 0.f, 0.f);
    float4 s2 = make_float4(0.f, 0.f, 0.f, 0.f);
    #pragma unroll
    for (int p = 0; p < 4; p++) {
        float lo[4], hi[4];
        #pragma unroll
        for (int c = 0; c < 4; c++) {
            unsigned int ulo, uhi;
            asm("mov.b64 {%0,%1}, %2;" : "=r"(ulo), "=r"(uhi) : "l"(acc[c * 4 + p]));
            lo[c] = __uint_as_float(ulo);
            hi[c] = __uint_as_float(uhi);
        }
        #pragma unroll
        for (int half = 0; half < 2; half++) {
            int row = row0 + warp * 8 + 2 * p + half;
            if (row < NN) {
                const float* vv = half ? hi : lo;
                float4 o;
                o.x = vv[0] + bb.x;
                o.y = vv[1] + bb.y;
                o.z = vv[2] + bb.z;
                o.w = vv[3] + bb.w;
                out[(size_t)row * 32 + lane] = o;
                s.x += o.x; s.y += o.y; s.z += o.z; s.w += o.w;
                s2.x += o.x * o.x; s2.y += o.y * o.y;
                s2.z += o.z * o.z; s2.w += o.w * o.w;
            }
        }
    }

    *reinterpret_cast<float4*>(&rsum[warp * 128 + lane * 4]) = s;
    *reinterpret_cast<float4*>(&rsq[warp * 128 + lane * 4])  = s2;
    __syncthreads();
    if (tid < 128) {
        float a = 0.f, b2 = 0.f;
        #pragma unroll
        for (int w = 0; w < 8; w++) {
            a  += rsum[w * 128 + tid];
            b2 += rsq[w * 128 + tid];
        }
        atomicAdd(&g_colsum[tid], a);
        atomicAdd(&g_colsq[tid], b2);
    }
}

// ===========================================================================
// GEMM2 (FFMA2, BN+ReLU applied on tile load):  out = relu(a*h+b) @ W2^T + b2
// ===========================================================================
__global__ void __launch_bounds__(256, 2)
gemm2_kernel(const float4* __restrict__ Z, const float* __restrict__ W,
             const float* __restrict__ bias, float4* __restrict__ out)
{
    extern __shared__ float sm[];
    float* Zt = sm;                       // [128][ZT_S]
    float* Ws = sm + 128 * ZT_S;          // [128][132]

    const int tid  = threadIdx.x;
    const int lane = tid & 31;
    const int warp = tid >> 5;
    const int row0 = blockIdx.x * 64;

    #pragma unroll 8
    for (int idx = tid; idx < 128 * 128; idx += 256) {
        int j = idx >> 7, k = idx & 127;
        Ws[k * 132 + j] = W[idx];
    }

    #pragma unroll 8
    for (int i4 = tid; i4 < 64 * 32; i4 += 256) {
        int r = i4 >> 5, c4 = i4 & 31;
        int row = row0 + r;
        float4 v = make_float4(0.f, 0.f, 0.f, 0.f);
        if (row < NN) {
            v = Z[(size_t)row * 32 + c4];
            int c = c4 * 4;
            v.x = fmaxf(fmaf(g_bncoef[c + 0], v.x, g_bncoef[DD + c + 0]), 0.f);
            v.y = fmaxf(fmaf(g_bncoef[c + 1], v.y, g_bncoef[DD + c + 1]), 0.f);
            v.z = fmaxf(fmaf(g_bncoef[c + 2], v.z, g_bncoef[DD + c + 2]), 0.f);
            v.w = fmaxf(fmaf(g_bncoef[c + 3], v.w, g_bncoef[DD + c + 3]), 0.f);
        }
        int c = c4 * 4;
        Zt[(c + 0) * ZT_S + r] = v.x;
        Zt[(c + 1) * ZT_S + r] = v.y;
        Zt[(c + 2) * ZT_S + r] = v.z;
        Zt[(c + 3) * ZT_S + r] = v.w;
    }
    __syncthreads();

    unsigned long long acc[16];
    #pragma unroll
    for (int i = 0; i < 16; i++) acc[i] = 0ULL;

    const float* ztbase = Zt + warp * 8;
    #pragma unroll 2
    for (int k = 0; k < 128; k++) {
        unsigned long long zp[4];
        #pragma unroll
        for (int p = 0; p < 4; p++)
            zp[p] = *reinterpret_cast<const unsigned long long*>(&ztbase[k * ZT_S + 2 * p]);
        float4 bv = *reinterpret_cast<const float4*>(&Ws[k * 132 + lane * 4]);
        unsigned long long wp[4];
        asm("mov.b64 %0, {%1,%1};" : "=l"(wp[0]) : "r"(__float_as_uint(bv.x)));
        asm("mov.b64 %0, {%1,%1};" : "=l"(wp[1]) : "r"(__float_as_uint(bv.y)));
        asm("mov.b64 %0, {%1,%1};" : "=l"(wp[2]) : "r"(__float_as_uint(bv.z)));
        asm("mov.b64 %0, {%1,%1};" : "=l"(wp[3]) : "r"(__float_as_uint(bv.w)));
        #pragma unroll
        for (int c = 0; c < 4; c++) {
            #pragma unroll
            for (int p = 0; p < 4; p++) {
                asm("fma.rn.f32x2 %0, %1, %2, %3;"
                    : "=l"(acc[c * 4 + p])
                    : "l"(zp[p]), "l"(wp[c]), "l"(acc[c * 4 + p]));
            }
        }
    }

    float4 bb = *reinterpret_cast<const float4*>(&bias[lane * 4]);

    #pragma unroll
    for (int p = 0; p < 4; p++) {
        float lo[4], hi[4];
        #pragma unroll
        for (int c = 0; c < 4; c++) {
            unsigned int ulo, uhi;
            asm("mov.b64 {%0,%1}, %2;" : "=r"(ulo), "=r"(uhi) : "l"(acc[c * 4 + p]));
            lo[c] = __uint_as_float(ulo);
            hi[c] = __uint_as_float(uhi);
        }
        #pragma unroll
        for (int half = 0; half < 2; half++) {
            int row = row0 + warp * 8 + 2 * p + half;
            if (row < NN) {
                const float* vv = half ? hi : lo;
                float4 o;
                o.x = vv[0] + bb.x;
                o.y = vv[1] + bb.y;
                o.z = vv[2] + bb.z;
                o.w = vv[3] + bb.w;
                out[(size_t)row * 32 + lane] = o;
            }
        }
    }
}

// ---------------------------------------------------------------------------
__global__ void bn_finalize(const float* __restrict__ gamma, const float* __restrict__ beta) {
    int j = threadIdx.x;
    float invn = 1.0f / (float)NN;
    float mean = g_colsum[j] * invn;
    float var  = g_colsq[j] * invn - mean * mean;
    float a = gamma[j] * rsqrtf(var + BN_EPS);
    g_bncoef[j]      = a;
    g_bncoef[DD + j] = beta[j] - mean * a;
}

// ---------------------------------------------------------------------------
extern "C" void kernel_launch(void* const* d_in, const int* in_sizes, int n_in,
                              void* d_out, int out_size) {
    const float* x     = (const float*)d_in[0];
    const void*  ei    = d_in[1];
    const float* eps   = (const float*)d_in[2];
    const float* W1    = (const float*)d_in[3];
    const float* b1    = (const float*)d_in[4];
    const float* gamma = (const float*)d_in[5];
    const float* beta  = (const float*)d_in[6];
    const float* W2    = (const float*)d_in[7];
    const float* b2    = (const float*)d_in[8];

    void* h_p = nullptr;
    cudaGetSymbolAddress(&h_p, g_h4);
    const float4* h4 = (const float4*)h_p;

    // smem: Zt 128*66 + Ws 128*132 + stats 2*8*128 floats = 109,568 B (2 CTAs/SM)
    const int SMEM1 = (128 * ZT_S + 128 * 132 + 2 * 8 * 128) * (int)sizeof(float);
    const int SMEM2 = (128 * ZT_S + 128 * 132) * (int)sizeof(float);
    cudaFuncSetAttribute(fused_gemm1_kernel,
                         cudaFuncAttributeMaxDynamicSharedMemorySize, SMEM1);
    cudaFuncSetAttribute(gemm2_kernel,
                         cudaFuncAttributeMaxDynamicSharedMemorySize, SMEM2);

    // 0) dtype detect + (fp16 mirror, zero) fused
    detect_kernel<<<1, 1>>>((const long long*)ei);
    prep_kernel<<<(NN * 32 + 255) / 256, 256>>>((const float4*)x);
    // 1) CSR build
    hist_kernel<<<(NE + 255) / 256, 256>>>(ei);
    scan_block_kernel<<<NBLK1, SCAN_B>>>();
    scan_top_kernel<<<1, 256>>>();
    scan_add_kernel<<<NBLK1, SCAN_B>>>();
    fill_kernel<<<(NE + 255) / 256, 256>>>(ei);
    // 2+3) fused gather + GEMM1 (+bias, +column stats)
    {
        int blocks = (NN + 63) / 64;
        fused_gemm1_kernel<<<blocks, 256, SMEM1>>>((const float4*)x, eps, W1, b1, (float4*)h_p);
    }
    // 4) BN coefficients
    bn_finalize<<<1, DD>>>(gamma, beta);
    // 5) GEMM2 (+BN+ReLU on input)
    {
        int blocks = (NN + 63) / 64;
        gemm2_kernel<<<blocks, 256, SMEM2>>>(h4, W2, b2, (float4*)d_out);
    }
}

// round 17
// speedup vs baseline: 1.0559x; 1.0559x over previous
#include <cuda_runtime.h>
#include <cuda_fp16.h>
#include <cstdint>

#define NN 100000
#define DD 128
#define NE 1600000
#define BN_EPS 1e-5f
#define SCAN_B 512
#define NBLK1 ((NN + SCAN_B - 1) / SCAN_B)   // 196

typedef unsigned long long ull;

// Scratch (device globals)
__device__ float4 g_hpre4[(size_t)NN * 32];   // 51.2 MB
__device__ float4 g_h4[(size_t)NN * 32];      // 51.2 MB
__device__ uint2  g_xh2[(size_t)NN * 32];     // 25.6 MB fp16 mirror of x
__device__ ull    g_w1d[128 * 128];           // W1 pre-dup [k][c][l] (1 MBish? 128KB)
__device__ ull    g_w2d[128 * 128];           // W2 pre-dup
__device__ float  g_colsum[DD];
__device__ float  g_colsq[DD];
__device__ float  g_bncoef[2 * DD];
__device__ int    g_is64;
// CSR scratch
__device__ int    g_deg[NN];
__device__ int    g_off[NN];
__device__ int    g_cur[NN];
__device__ int    g_adj[2 * NE];              // 12.8 MB
__device__ int    g_bsum[NBLK1];
__device__ int    g_bpre[NBLK1];

// ---------------------------------------------------------------------------
__global__ void detect_kernel(const long long* __restrict__ ei) {
    long long ok = 1;
    #pragma unroll
    for (int i = 0; i < 16; i++) {
        long long v = ei[i];
        if (v < 0 || v >= NN) ok = 0;
    }
    g_is64 = (int)ok;
}

__device__ __forceinline__ void load_edge(const void* ei_raw, int e, int& s, int& d) {
    if (g_is64) {
        const long long* ei = (const long long*)ei_raw;
        s = (int)ei[e]; d = (int)ei[NE + e];
    } else {
        const int* ei = (const int*)ei_raw;
        s = ei[e]; d = ei[NE + e];
    }
}

// ---------------------------------------------------------------------------
// prep: fp16 mirror of x + zero deg/stats + build duplicated-pair W images
//   g_wXd[k*128 + c*32 + l] = dup(W[(4l+c)*128 + k])   (ull = {w,w})
// ---------------------------------------------------------------------------
#define PREP_XBLK ((NN * 32 + 255) / 256)   // 12500
__global__ void prep_kernel(const float4* __restrict__ x,
                            const float* __restrict__ W1,
                            const float* __restrict__ W2) {
    int b = blockIdx.x;
    if (b < PREP_XBLK) {
        int i = b * 256 + threadIdx.x;
        if (i < NN * 32) {
            float4 v = x[i];
            half2 lo = __floats2half2_rn(v.x, v.y);
            half2 hi = __floats2half2_rn(v.z, v.w);
            uint2 u;
            u.x = *reinterpret_cast<unsigned int*>(&lo);
            u.y = *reinterpret_cast<unsigned int*>(&hi);
            g_xh2[i] = u;
        }
        if (i < NN) g_deg[i] = 0;
        if (i < DD) { g_colsum[i] = 0.0f; g_colsq[i] = 0.0f; }
    } else {
        int idx = (b - PREP_XBLK) * 256 + threadIdx.x;   // 0..32767
        if (idx < 2 * 16384) {
            int buf  = idx >> 14;
            int rest = idx & 16383;
            int l = rest & 31;
            int c = (rest >> 5) & 3;
            int k = rest >> 7;
            const float* W = buf ? W2 : W1;
            float w = W[(4 * l + c) * 128 + k];
            unsigned int u = __float_as_uint(w);
            ull d = ((ull)u << 32) | (ull)u;
            if (buf) g_w2d[rest] = d; else g_w1d[rest] = d;
        }
    }
}

// ---------------------------------------------------------------------------
__global__ void hist_kernel(const void* __restrict__ ei_raw) {
    int e = blockIdx.x * blockDim.x + threadIdx.x;
    if (e >= NE) return;
    int s, d; load_edge(ei_raw, e, s, d);
    atomicAdd(&g_deg[d], 1);
    atomicAdd(&g_deg[s], 1);
}

// ---------------------------------------------------------------------------
__global__ void scan_block_kernel() {
    __shared__ int sh[SCAN_B];
    int tid = threadIdx.x;
    int i = blockIdx.x * SCAN_B + tid;
    int v = (i < NN) ? g_deg[i] : 0;
    sh[tid] = v;
    __syncthreads();
    #pragma unroll
    for (int o = 1; o < SCAN_B; o <<= 1) {
        int t = (tid >= o) ? sh[tid - o] : 0;
        __syncthreads();
        sh[tid] += t;
        __syncthreads();
    }
    if (i < NN) g_off[i] = sh[tid] - v;
    if (tid == SCAN_B - 1) g_bsum[blockIdx.x] = sh[tid];
}

__global__ void scan_top_kernel() {
    __shared__ int sh[256];
    int tid = threadIdx.x;
    int v = (tid < NBLK1) ? g_bsum[tid] : 0;
    sh[tid] = v;
    __syncthreads();
    #pragma unroll
    for (int o = 1; o < 256; o <<= 1) {
        int t = (tid >= o) ? sh[tid - o] : 0;
        __syncthreads();
        sh[tid] += t;
        __syncthreads();
    }
    if (tid < NBLK1) g_bpre[tid] = sh[tid] - v;
}

__global__ void scan_add_kernel() {
    int i = blockIdx.x * SCAN_B + threadIdx.x;
    if (i < NN) {
        int o = g_off[i] + g_bpre[blockIdx.x];
        g_off[i] = o;
        g_cur[i] = o;
    }
}

// ---------------------------------------------------------------------------
__global__ void fill_kernel(const void* __restrict__ ei_raw) {
    int e = blockIdx.x * blockDim.x + threadIdx.x;
    if (e >= NE) return;
    int s, d; load_edge(ei_raw, e, s, d);
    int p0 = atomicAdd(&g_cur[d], 1);
    g_adj[p0] = s;
    int p1 = atomicAdd(&g_cur[s], 1);
    g_adj[p1] = d;
}

// ---------------------------------------------------------------------------
// gather: one warp per node; unroll-8. fp16 neighbor rows, fp32 accum,
// exact fp32 self-term.
// ---------------------------------------------------------------------------
__global__ void gather_kernel(const float4* __restrict__ x,
                              const float* __restrict__ eps_p) {
    int w = (blockIdx.x * blockDim.x + threadIdx.x) >> 5;
    if (w >= NN) return;
    int lane = threadIdx.x & 31;
    float sc = 2.0f + *eps_p;

    float4 xv = x[(size_t)w * 32 + lane];
    float4 acc = make_float4(xv.x * sc, xv.y * sc, xv.z * sc, xv.w * sc);

    const int* adj = g_adj + g_off[w];
    int deg = g_deg[w];
    int i = 0;
    for (; i + 8 <= deg; i += 8) {
        int n[8];
        #pragma unroll
        for (int j = 0; j < 8; j++) n[j] = adj[i + j];
        uint2 u[8];
        #pragma unroll
        for (int j = 0; j < 8; j++) u[j] = g_xh2[(size_t)n[j] * 32 + lane];
        #pragma unroll
        for (int j = 0; j < 8; j++) {
            float2 a = __half22float2(*reinterpret_cast<half2*>(&u[j].x));
            float2 b = __half22float2(*reinterpret_cast<half2*>(&u[j].y));
            acc.x += a.x; acc.y += a.y; acc.z += b.x; acc.w += b.y;
        }
    }
    for (; i < deg; i++) {
        uint2 u0 = g_xh2[(size_t)adj[i] * 32 + lane];
        float2 a0 = __half22float2(*reinterpret_cast<half2*>(&u0.x));
        float2 b0 = __half22float2(*reinterpret_cast<half2*>(&u0.y));
        acc.x += a0.x; acc.y += a0.y; acc.z += b0.x; acc.w += b0.y;
    }
    g_hpre4[(size_t)w * 32 + lane] = acc;
}

// ===========================================================================
// GEMM v3 (FFMA2, pre-dup W):  out[N,128] = f(Z[N,128]) @ W^T + bias
// 512 threads (16 warps), 1 CTA/SM. Tile 128 rows x 128 cols, K=128.
//  - Wd smem [k][c][lane] ull dup pairs: straight 128KB copy (LDG.128/STS.128,
//    conflict-free); mainloop LDS.64 lane-contiguous (conflict-free), no MOVs.
//  - Zt transposed floats [k][r], stride 130.
// Each warp: 8 rows = 4 row-pairs; lane: cols 4*lane..+3. 16 FFMA2/k.
// ===========================================================================
#define ZT3_S 130   // floats per Zt row (128 + 2 pad); k-row = 520 B

#define SM_ZT   0
#define SM_WD   66560                    // 128*130*4
#define SM_ST   (66560 + 131072)         // + 128*128*8
#define SM_TOT  (SM_ST + 2 * 16 * 128 * 4)   // +16KB stats = 214,016

template <bool BN_IN, bool STATS>
__global__ void __launch_bounds__(512, 1)
gemm3_kernel(const float4* __restrict__ Z, const ull* __restrict__ Wd_g,
             const float* __restrict__ bias, float4* __restrict__ out)
{
    extern __shared__ char smb[];
    float* Zt   = (float*)(smb + SM_ZT);
    ull*   Wd   = (ull*)(smb + SM_WD);
    float* rsum = (float*)(smb + SM_ST);
    float* rsq  = rsum + 16 * 128;

    const int tid  = threadIdx.x;
    const int lane = tid & 31;
    const int warp = tid >> 5;
    const int row0 = blockIdx.x * 128;

    // ---- W copy: 128KB, coalesced, conflict-free
    {
        const uint4* wg = (const uint4*)Wd_g;
        uint4* ws = (uint4*)Wd;
        #pragma unroll
        for (int it = 0; it < 16; it++)
            ws[tid + it * 512] = wg[tid + it * 512];
    }

    // ---- Z tile -> transposed smem (optionally BN+ReLU on load)
    #pragma unroll
    for (int it = 0; it < 8; it++) {
        int i4 = tid + it * 512;            // 0..4095
        int r = i4 >> 5, c4 = i4 & 31;
        int row = row0 + r;
        float4 v = make_float4(0.f, 0.f, 0.f, 0.f);
        if (row < NN) {
            v = Z[(size_t)row * 32 + c4];
            if (BN_IN) {
                int c = c4 * 4;
                v.x = fmaxf(fmaf(g_bncoef[c + 0], v.x, g_bncoef[DD + c + 0]), 0.f);
                v.y = fmaxf(fmaf(g_bncoef[c + 1], v.y, g_bncoef[DD + c + 1]), 0.f);
                v.z = fmaxf(fmaf(g_bncoef[c + 2], v.z, g_bncoef[DD + c + 2]), 0.f);
                v.w = fmaxf(fmaf(g_bncoef[c + 3], v.w, g_bncoef[DD + c + 3]), 0.f);
            }
        }
        int c = c4 * 4;
        Zt[(c + 0) * ZT3_S + r] = v.x;
        Zt[(c + 1) * ZT3_S + r] = v.y;
        Zt[(c + 2) * ZT3_S + r] = v.z;
        Zt[(c + 3) * ZT3_S + r] = v.w;
    }
    __syncthreads();

    // ---- mainloop
    ull acc[16];
    #pragma unroll
    for (int i = 0; i < 16; i++) acc[i] = 0ULL;

    const char* ztb = (const char*)Zt + warp * 32;      // warp's 4 pairs: +0,8,16,24
    const char* wdb = (const char*)Wd + lane * 8;       // +c*256
    #pragma unroll 4
    for (int k = 0; k < 128; k++) {
        const char* zr = ztb + k * (ZT3_S * 4);
        const char* wr = wdb + k * 1024;
        ull zp[4], wp[4];
        #pragma unroll
        for (int p = 0; p < 4; p++) zp[p] = *(const ull*)(zr + p * 8);
        #pragma unroll
        for (int c = 0; c < 4; c++) wp[c] = *(const ull*)(wr + c * 256);
        #pragma unroll
        for (int c = 0; c < 4; c++) {
            #pragma unroll
            for (int p = 0; p < 4; p++) {
                asm("fma.rn.f32x2 %0, %1, %2, %3;"
                    : "=l"(acc[c * 4 + p])
                    : "l"(zp[p]), "l"(wp[c]), "l"(acc[c * 4 + p]));
            }
        }
    }

    float4 bb = *reinterpret_cast<const float4*>(&bias[lane * 4]);

    float4 s  = make_float4(0.f, 0.f, 0.f, 0.f);
    float4 s2 = make_float4(0.f, 0.f, 0.f, 0.f);
    #pragma unroll
    for (int p = 0; p < 4; p++) {
        float lo[4], hi[4];
        #pragma unroll
        for (int c = 0; c < 4; c++) {
            unsigned int ulo, uhi;
            asm("mov.b64 {%0,%1}, %2;" : "=r"(ulo), "=r"(uhi) : "l"(acc[c * 4 + p]));
            lo[c] = __uint_as_float(ulo);
            hi[c] = __uint_as_float(uhi);
        }
        #pragma unroll
        for (int half = 0; half < 2; half++) {
            int row = row0 + warp * 8 + 2 * p + half;
            if (row < NN) {
                const float* vv = half ? hi : lo;
                float4 o;
                o.x = vv[0] + bb.x;
                o.y = vv[1] + bb.y;
                o.z = vv[2] + bb.z;
                o.w = vv[3] + bb.w;
                out[(size_t)row * 32 + lane] = o;
                if (STATS) {
                    s.x += o.x; s.y += o.y; s.z += o.z; s.w += o.w;
                    s2.x += o.x * o.x; s2.y += o.y * o.y;
                    s2.z += o.z * o.z; s2.w += o.w * o.w;
                }
            }
        }
    }

    if (STATS) {
        *reinterpret_cast<float4*>(&rsum[warp * 128 + lane * 4]) = s;
        *reinterpret_cast<float4*>(&rsq[warp * 128 + lane * 4])  = s2;
        __syncthreads();
        if (tid < 128) {
            float a = 0.f, b2 = 0.f;
            #pragma unroll
            for (int w = 0; w < 16; w++) {
                a  += rsum[w * 128 + tid];
                b2 += rsq[w * 128 + tid];
            }
            atomicAdd(&g_colsum[tid], a);
            atomicAdd(&g_colsq[tid], b2);
        }
    }
}

// ---------------------------------------------------------------------------
__global__ void bn_finalize(const float* __restrict__ gamma, const float* __restrict__ beta) {
    int j = threadIdx.x;
    float invn = 1.0f / (float)NN;
    float mean = g_colsum[j] * invn;
    float var  = g_colsq[j] * invn - mean * mean;
    float a = gamma[j] * rsqrtf(var + BN_EPS);
    g_bncoef[j]      = a;
    g_bncoef[DD + j] = beta[j] - mean * a;
}

// ---------------------------------------------------------------------------
extern "C" void kernel_launch(void* const* d_in, const int* in_sizes, int n_in,
                              void* d_out, int out_size) {
    const float* x     = (const float*)d_in[0];
    const void*  ei    = d_in[1];
    const float* eps   = (const float*)d_in[2];
    const float* W1    = (const float*)d_in[3];
    const float* b1    = (const float*)d_in[4];
    const float* gamma = (const float*)d_in[5];
    const float* beta  = (const float*)d_in[6];
    const float* W2    = (const float*)d_in[7];
    const float* b2    = (const float*)d_in[8];

    void* hpre_p = nullptr;
    void* h_p    = nullptr;
    void* w1d_p  = nullptr;
    void* w2d_p  = nullptr;
    cudaGetSymbolAddress(&hpre_p, g_hpre4);
    cudaGetSymbolAddress(&h_p, g_h4);
    cudaGetSymbolAddress(&w1d_p, g_w1d);
    cudaGetSymbolAddress(&w2d_p, g_w2d);
    const float4* hpre4 = (const float4*)hpre_p;
    const float4* h4    = (const float4*)h_p;

    cudaFuncSetAttribute(gemm3_kernel<false, true>,
                         cudaFuncAttributeMaxDynamicSharedMemorySize, SM_TOT);
    cudaFuncSetAttribute(gemm3_kernel<true, false>,
                         cudaFuncAttributeMaxDynamicSharedMemorySize, SM_TOT);

    // 0) dtype detect + prep (fp16 mirror, zero, W pre-dup)
    detect_kernel<<<1, 1>>>((const long long*)ei);
    prep_kernel<<<PREP_XBLK + 128, 256>>>((const float4*)x, W1, W2);
    // 1) CSR build
    hist_kernel<<<(NE + 255) / 256, 256>>>(ei);
    scan_block_kernel<<<NBLK1, SCAN_B>>>();
    scan_top_kernel<<<1, 256>>>();
    scan_add_kernel<<<NBLK1, SCAN_B>>>();
    fill_kernel<<<(NE + 255) / 256, 256>>>(ei);
    // 2) gather
    gather_kernel<<<(NN * 32 + 255) / 256, 256>>>((const float4*)x, eps);
    // 3) GEMM1 (+bias, +column stats)
    {
        int blocks = (NN + 127) / 128;
        gemm3_kernel<false, true><<<blocks, 512, SM_TOT>>>(hpre4, (const ull*)w1d_p, b1, (float4*)h_p);
    }
    // 4) BN coefficients
    bn_finalize<<<1, DD>>>(gamma, beta);
    // 5) GEMM2 (+BN+ReLU on input)
    {
        int blocks = (NN + 127) / 128;
        gemm3_kernel<true, false><<<blocks, 512, SM_TOT>>>(h4, (const ull*)w2d_p, b2, (float4*)d_out);
    }
}